// round 1
// baseline (speedup 1.0000x reference)
#include <cuda_runtime.h>
#include <cuda_bf16.h>

#define HH 1024
#define WW 2048
#define HWSZ (HH * WW)
#define NC 19
#define RAD 16
#define INV_LOG19 0.3396224f   // 1 / ln(19)

// -------- scratch (device globals: allocation-free per harness rules) -------
__device__ unsigned char g_predict[HWSZ];           // argmax class per pixel
__device__ float         g_wpe[HWSZ];               // weighted pixel entropy / ln19
__device__ unsigned char g_vcount[NC * HWSZ];       // vertical 33-window class counts
__device__ float         g_vwpe[HWSZ];              // vertical 33-window entropy sums

// ============================================================================
// Pass A: per-pixel softmax entropy + argmax + weighted entropy
// ============================================================================
__global__ __launch_bounds__(256) void passA(const float* __restrict__ logit,
                                             const float* __restrict__ cw) {
    int i = blockIdx.x * blockDim.x + threadIdx.x;
    if (i >= HWSZ) return;

    float v[NC];
#pragma unroll
    for (int c = 0; c < NC; c++) v[c] = logit[c * HWSZ + i];

    float m = v[0];
    int am = 0;
#pragma unroll
    for (int c = 1; c < NC; c++) {
        if (v[c] > m) { m = v[c]; am = c; }
    }

    float S = 0.f, T = 0.f;
#pragma unroll
    for (int c = 0; c < NC; c++) {
        float d = v[c] - m;
        float e = __expf(d);
        S += e;
        T += e * d;
    }
    // entropy = -sum p log p = log S - (1/S) * sum e_i * (x_i - m)
    float ent = __logf(S) - T * __frcp_rn(S);

    g_predict[i] = (unsigned char)am;
    g_wpe[i] = ent * cw[am] * INV_LOG19;
}

// ============================================================================
// Pass B: vertical 33-tap box filter.
// Thread = one column x, CHB output rows. Per-class counts packed into 3
// uint64 words (8-bit lanes, max value 33, no inter-lane carry possible).
// ============================================================================
#define CHB 32

__device__ __forceinline__ void pk_add(unsigned long long& w0,
                                       unsigned long long& w1,
                                       unsigned long long& w2, int cls) {
    unsigned long long inc = 1ull << ((cls & 7) * 8);
    if (cls < 8)       w0 += inc;
    else if (cls < 16) w1 += inc;
    else               w2 += inc;
}
__device__ __forceinline__ void pk_sub(unsigned long long& w0,
                                       unsigned long long& w1,
                                       unsigned long long& w2, int cls) {
    unsigned long long dec = 1ull << ((cls & 7) * 8);
    if (cls < 8)       w0 -= dec;
    else if (cls < 16) w1 -= dec;
    else               w2 -= dec;
}

__global__ __launch_bounds__(256) void passB() {
    int x  = blockIdx.x * blockDim.x + threadIdx.x;   // column
    int y0 = blockIdx.y * CHB;                        // first output row

    unsigned long long w0 = 0, w1 = 0, w2 = 0;
    float fs = 0.f;

    int ys = y0 - RAD; if (ys < 0) ys = 0;
    int ye = y0 + RAD; if (ye > HH - 1) ye = HH - 1;
    for (int y = ys; y <= ye; ++y) {
        int idx = y * WW + x;
        int cls = g_predict[idx];
        fs += g_wpe[idx];
        pk_add(w0, w1, w2, cls);
    }

#pragma unroll 4
    for (int k = 0; k < CHB; k++) {
        int y = y0 + k;
        int base = y * WW + x;
        g_vwpe[base] = fs;
#pragma unroll
        for (int c = 0; c < 8; c++)
            g_vcount[c * HWSZ + base] = (unsigned char)(w0 >> (8 * c));
#pragma unroll
        for (int c = 8; c < 16; c++)
            g_vcount[c * HWSZ + base] = (unsigned char)(w1 >> (8 * (c - 8)));
#pragma unroll
        for (int c = 16; c < NC; c++)
            g_vcount[c * HWSZ + base] = (unsigned char)(w2 >> (8 * (c - 16)));

        int ya = y + RAD + 1;
        if (ya < HH) {
            int ia = ya * WW + x;
            int cls = g_predict[ia];
            fs += g_wpe[ia];
            pk_add(w0, w1, w2, cls);
        }
        int yr = y - RAD;
        if (yr >= 0) {
            int ir = yr * WW + x;
            int cls = g_predict[ir];
            fs -= g_wpe[ir];
            pk_sub(w0, w1, w2, cls);
        }
    }
}

// ============================================================================
// Pass C: horizontal 33-tap box filter + impurity / uncertainty / score.
// Thread = one row y, CHC output columns, sliding 19 int register sums.
// impurity = (log(count) - (1/count) * sum cnt*log(cnt + 1e-6*count)) / ln19
// which is algebraically EXACT vs reference's -sum d*log(d+1e-6).
// ============================================================================
#define CHC 32
#define NCHK (WW / CHC)   // 64 chunks per row

__global__ __launch_bounds__(256) void passC(float* __restrict__ out) {
    int tid = blockIdx.x * blockDim.x + threadIdx.x;
    int j = tid & (NCHK - 1);
    int y = tid >> 6;               // NCHK = 64
    if (y >= HH) return;
    int x0 = j * CHC;
    int rowbase = y * WW;

    int s[NC];
#pragma unroll
    for (int c = 0; c < NC; c++) s[c] = 0;
    float fs = 0.f;

    int xs = x0 - RAD; if (xs < 0) xs = 0;
    int xe = x0 + RAD; if (xe > WW - 1) xe = WW - 1;
    for (int x = xs; x <= xe; ++x) {
#pragma unroll
        for (int c = 0; c < NC; c++) s[c] += g_vcount[c * HWSZ + rowbase + x];
        fs += g_vwpe[rowbase + x];
    }

    for (int k = 0; k < CHC; k++) {
        int x = x0 + k;

        int count = 0;
#pragma unroll
        for (int c = 0; c < NC; c++) count += s[c];
        float fcount = (float)count;
        float invc = __frcp_rn(fcount);
        float eps = 1e-6f * fcount;

        float acc = 0.f;
#pragma unroll
        for (int c = 0; c < NC; c++) {
            float sc = (float)s[c];
            acc += sc * __logf(sc + eps);   // sc==0 term contributes exactly 0
        }
        float impurity = (__logf(fcount) - acc * invc) * INV_LOG19;
        float unc = fs * invc;

        int o = rowbase + x;
        out[o]             = impurity * unc;   // score
        out[HWSZ + o]      = impurity;         // region_impurity
        out[2 * HWSZ + o]  = unc;              // prediction_uncertainty

        int xa = x + RAD + 1;
        if (xa < WW) {
#pragma unroll
            for (int c = 0; c < NC; c++) s[c] += g_vcount[c * HWSZ + rowbase + xa];
            fs += g_vwpe[rowbase + xa];
        }
        int xr = x - RAD;
        if (xr >= 0) {
#pragma unroll
            for (int c = 0; c < NC; c++) s[c] -= g_vcount[c * HWSZ + rowbase + xr];
            fs -= g_vwpe[rowbase + xr];
        }
    }
}

// ============================================================================
extern "C" void kernel_launch(void* const* d_in, const int* in_sizes, int n_in,
                              void* d_out, int out_size) {
    const float* logit = (const float*)d_in[0];
    const float* cw    = (const float*)d_in[1];
    float* out = (float*)d_out;

    passA<<<HWSZ / 256, 256>>>(logit, cw);
    {
        dim3 grid(WW / 256, HH / CHB);
        passB<<<grid, 256>>>();
    }
    passC<<<(HH * NCHK) / 256, 256>>>(out);
}

// round 2
// speedup vs baseline: 1.7534x; 1.7534x over previous
#include <cuda_runtime.h>
#include <cuda_bf16.h>

#define HH 1024
#define WW 2048
#define HWSZ (HH * WW)
#define NC 19
#define RAD 16
#define INV_LOG19 0.3396224f   // 1 / ln(19)

// -------- scratch (device globals: allocation-free per harness rules) -------
__device__ unsigned char g_predict[HWSZ];   // argmax class per pixel
__device__ float         g_wpe[HWSZ];       // weighted pixel entropy / ln19
// 32B record per pixel: [c0..c7][c8..c15][c16..c18,pad][pad*5][fs][pad]
__device__ uint4         g_rec[2 * HWSZ];   // 64 MB

// ============================================================================
// Pass A: per-pixel softmax entropy + argmax + weighted entropy
// ============================================================================
__global__ __launch_bounds__(256) void passA(const float* __restrict__ logit,
                                             const float* __restrict__ cw) {
    int i = blockIdx.x * blockDim.x + threadIdx.x;
    if (i >= HWSZ) return;

    float v[NC];
#pragma unroll
    for (int c = 0; c < NC; c++) v[c] = logit[c * HWSZ + i];

    float m = v[0];
    int am = 0;
#pragma unroll
    for (int c = 1; c < NC; c++) {
        if (v[c] > m) { m = v[c]; am = c; }
    }

    float S = 0.f, T = 0.f;
#pragma unroll
    for (int c = 0; c < NC; c++) {
        float d = v[c] - m;
        float e = __expf(d);
        S += e;
        T += e * d;
    }
    float ent = __logf(S) - T * __frcp_rn(S);

    g_predict[i] = (unsigned char)am;
    g_wpe[i] = ent * cw[am] * INV_LOG19;
}

// ============================================================================
// Pass B: vertical 33-tap box filter -> packed 32B records (coalesced STG.128)
// ============================================================================
#define CHB 32

__device__ __forceinline__ void pk_add(unsigned long long& w0,
                                       unsigned long long& w1,
                                       unsigned long long& w2, int cls) {
    unsigned long long inc = 1ull << ((cls & 7) * 8);
    if (cls < 8)       w0 += inc;
    else if (cls < 16) w1 += inc;
    else               w2 += inc;
}
__device__ __forceinline__ void pk_sub(unsigned long long& w0,
                                       unsigned long long& w1,
                                       unsigned long long& w2, int cls) {
    unsigned long long dec = 1ull << ((cls & 7) * 8);
    if (cls < 8)       w0 -= dec;
    else if (cls < 16) w1 -= dec;
    else               w2 -= dec;
}

__global__ __launch_bounds__(256) void passB() {
    int x  = blockIdx.x * blockDim.x + threadIdx.x;   // column (lane-consecutive)
    int y0 = blockIdx.y * CHB;

    unsigned long long w0 = 0, w1 = 0, w2 = 0;
    float fs = 0.f;

    int ys = y0 - RAD; if (ys < 0) ys = 0;
    int ye = y0 + RAD; if (ye > HH - 1) ye = HH - 1;
    for (int y = ys; y <= ye; ++y) {
        int idx = y * WW + x;
        fs += g_wpe[idx];
        pk_add(w0, w1, w2, g_predict[idx]);
    }

#pragma unroll 4
    for (int k = 0; k < CHB; k++) {
        int y = y0 + k;
        int idx = y * WW + x;

        uint4 a, b;
        a.x = (unsigned)w0;  a.y = (unsigned)(w0 >> 32);
        a.z = (unsigned)w1;  a.w = (unsigned)(w1 >> 32);
        b.x = (unsigned)w2;  b.y = (unsigned)(w2 >> 32);
        b.z = __float_as_uint(fs);  b.w = 0;
        g_rec[2 * idx]     = a;
        g_rec[2 * idx + 1] = b;

        int ya = y + RAD + 1;
        if (ya < HH) {
            int ia = ya * WW + x;
            fs += g_wpe[ia];
            pk_add(w0, w1, w2, g_predict[ia]);
        }
        int yr = y - RAD;
        if (yr >= 0) {
            int ir = yr * WW + x;
            fs -= g_wpe[ir];
            pk_sub(w0, w1, w2, g_predict[ir]);
        }
    }
}

// ============================================================================
// Pass C: horizontal 33-tap box filter via SIMD 16-bit-lane sliding sums.
// Record fetch = 2x LDG.128 hitting one 32B sector. Outputs buffered to
// float4 stores. impurity algebra identical to reference (incl. eps).
// ============================================================================
#define CHC 32
#define NCHK (WW / CHC)   // 64 chunks per row

// unpack 4 bytes of w into two u32 halfword pairs
#define PLO(w) __byte_perm((w), 0, 0x4140)
#define PHI(w) __byte_perm((w), 0, 0x4342)

__device__ __forceinline__ void rec_add(unsigned* h, float& fs, int idx) {
    uint4 a = g_rec[2 * idx];
    uint4 b = g_rec[2 * idx + 1];
    h[0] += PLO(a.x); h[1] += PHI(a.x);
    h[2] += PLO(a.y); h[3] += PHI(a.y);
    h[4] += PLO(a.z); h[5] += PHI(a.z);
    h[6] += PLO(a.w); h[7] += PHI(a.w);
    h[8] += PLO(b.x); h[9] += PHI(b.x);   // classes 16..18 (+zero pad)
    fs += __uint_as_float(b.z);
}
__device__ __forceinline__ void rec_sub(unsigned* h, float& fs, int idx) {
    uint4 a = g_rec[2 * idx];
    uint4 b = g_rec[2 * idx + 1];
    h[0] -= PLO(a.x); h[1] -= PHI(a.x);
    h[2] -= PLO(a.y); h[3] -= PHI(a.y);
    h[4] -= PLO(a.z); h[5] -= PHI(a.z);
    h[6] -= PLO(a.w); h[7] -= PHI(a.w);
    h[8] -= PLO(b.x); h[9] -= PHI(b.x);
    fs -= __uint_as_float(b.z);
}

__global__ __launch_bounds__(256) void passC(float* __restrict__ out) {
    int tid = blockIdx.x * blockDim.x + threadIdx.x;
    int j = tid & (NCHK - 1);
    int y = tid >> 6;               // NCHK = 64
    if (y >= HH) return;
    int x0 = j * CHC;
    int rowbase = y * WW;

    unsigned h[10];
#pragma unroll
    for (int i = 0; i < 10; i++) h[i] = 0;
    float fs = 0.f;

    int xs = x0 - RAD; if (xs < 0) xs = 0;
    int xe = x0 + RAD; if (xe > WW - 1) xe = WW - 1;
    for (int x = xs; x <= xe; ++x) rec_add(h, fs, rowbase + x);

#pragma unroll 1
    for (int k4 = 0; k4 < CHC / 4; k4++) {
        float s4[4], i4[4], u4[4];
#pragma unroll
        for (int kk = 0; kk < 4; kk++) {
            int k = k4 * 4 + kk;
            int x = x0 + k;

            // count = sum of all 16-bit lanes (packed fold: max 10*1089 < 2^16)
            unsigned t = h[0] + h[1] + h[2] + h[3] + h[4]
                       + h[5] + h[6] + h[7] + h[8] + h[9];
            unsigned count = (t & 0xFFFFu) + (t >> 16);
            float fcount = (float)count;
            float invc = __frcp_rn(fcount);
            float eps = 1e-6f * fcount;

            float acc = 0.f;
#pragma unroll
            for (int p = 0; p < 10; p++) {
                float slo = (float)(h[p] & 0xFFFFu);
                float shi = (float)(h[p] >> 16);
                acc += slo * __logf(slo + eps);     // 0*log(eps) == 0
                if (!(p == 9))                       // lane 19 is pad (zero)
                    acc += shi * __logf(shi + eps);
            }
            float impurity = (__logf(fcount) - acc * invc) * INV_LOG19;
            float unc = fs * invc;

            s4[kk] = impurity * unc;
            i4[kk] = impurity;
            u4[kk] = unc;

            int xa = x + RAD + 1;
            if (xa < WW) rec_add(h, fs, rowbase + xa);
            int xr = x - RAD;
            if (xr >= 0) rec_sub(h, fs, rowbase + xr);
        }
        int o = rowbase + x0 + k4 * 4;
        *(float4*)(out + o)             = make_float4(s4[0], s4[1], s4[2], s4[3]);
        *(float4*)(out + HWSZ + o)      = make_float4(i4[0], i4[1], i4[2], i4[3]);
        *(float4*)(out + 2 * HWSZ + o)  = make_float4(u4[0], u4[1], u4[2], u4[3]);
    }
}

// ============================================================================
extern "C" void kernel_launch(void* const* d_in, const int* in_sizes, int n_in,
                              void* d_out, int out_size) {
    const float* logit = (const float*)d_in[0];
    const float* cw    = (const float*)d_in[1];
    float* out = (float*)d_out;

    passA<<<HWSZ / 256, 256>>>(logit, cw);
    {
        dim3 grid(WW / 256, HH / CHB);
        passB<<<grid, 256>>>();
    }
    passC<<<(HH * NCHK) / 256, 256>>>(out);
}